// round 10
// baseline (speedup 1.0000x reference)
#include <cuda_runtime.h>
#include <math.h>

#define NGRID 128
#define NG3 (NGRID*NGRID*NGRID)
#define CCH 32
#define RAD 4          // conv kernel radius; neglected mass ~3e-6 relative
#define MAXN 32768

__device__ float g_field0[NG3];   // 8 MB (scatter target / slab output / gather src)
__device__ float g_field1[NG3];   // 8 MB (z-conv out / slab input)
__device__ float g_s[MAXN];       // per-particle channel-summed feature

struct Taps { float t[RAD + 1]; };

// ---------------------------------------------------------------------------
// Fused zero + MLP. Grid = 2048 blocks x 256 threads.
// ---------------------------------------------------------------------------
__global__ __launch_bounds__(256)
void k_zero_mlp(const int* __restrict__ z, const float* __restrict__ emb,
                const float* __restrict__ W0, const float* __restrict__ b0,
                const float* __restrict__ W1, const float* __restrict__ b1,
                int n) {
    int gtid = blockIdx.x * 256 + threadIdx.x;
    reinterpret_cast<float4*>(g_field0)[gtid] = make_float4(0.f, 0.f, 0.f, 0.f);

    int mlp_blocks = (n + 255) / 256;
    if ((int)blockIdx.x >= mlp_blocks) return;

    __shared__ float sEmb[128 * CCH];
    __shared__ float sW0[CCH * CCH];
    __shared__ float sW1[CCH * CCH];
    __shared__ float sb0[CCH], sb1[CCH];
    for (int i = threadIdx.x; i < 128 * CCH; i += 256) sEmb[i] = emb[i];
    for (int i = threadIdx.x; i < CCH * CCH; i += 256) { sW0[i] = W0[i]; sW1[i] = W1[i]; }
    if (threadIdx.x < CCH) { sb0[threadIdx.x] = b0[threadIdx.x]; sb1[threadIdx.x] = b1[threadIdx.x]; }
    __syncthreads();

    int i = gtid;
    if (i >= n) return;
    int zi = z[i];
    float x[CCH], y[CCH];
    #pragma unroll
    for (int c = 0; c < CCH; c++) x[c] = sEmb[zi * CCH + c];
    #pragma unroll
    for (int r = 0; r < CCH; r++) {
        float a = sb0[r];
        #pragma unroll
        for (int c = 0; c < CCH; c++) a += sW0[r * CCH + c] * x[c];
        y[r] = a / (1.f + __expf(-a));               // silu
    }
    float s = 0.f;
    #pragma unroll
    for (int r = 0; r < CCH; r++) {
        float a = sb1[r];
        #pragma unroll
        for (int c = 0; c < CCH; c++) a += sW1[r * CCH + c] * y[c];
        s += a / (1.f + __expf(-a));                 // silu, then channel-sum
    }
    g_s[i] = s;
}

// ---------------------------------------------------------------------------
// Separable window, one WARP per particle.
// ---------------------------------------------------------------------------
__device__ __forceinline__ void warp_window(const float* __restrict__ pos, int i, int lane,
                                            float& w0, int& idx0, float& w1, int& idx1) {
    const float h = 10.0f / 128.0f;     // exact in fp32
    const float inv = 1.0f / h;
    float px = fmodf(__ldg(&pos[3 * i + 0]), 10.0f);
    float py = fmodf(__ldg(&pos[3 * i + 1]), 10.0f);
    float pz = fmodf(__ldg(&pos[3 * i + 2]), 10.0f);
    int bx = (int)floorf(px * inv);
    int by = (int)floorf(py * inv);
    int bz = (int)floorf(pz * inv);

    // lanes 0..11: one exp each (axis = lane>>2, offset = lane&3)
    int ax = lane >> 2, off = lane & 3;
    float pw = (ax == 0) ? px : (ax == 1) ? py : pz;
    int   bb = (ax == 0) ? bx : (ax == 1) ? by : bz;
    int cc = bb + off - 1;
    float d = (pw - (float)cc * h) * inv;
    float e = __expf(-0.5f * d * d);

    #pragma unroll
    for (int half = 0; half < 2; half++) {
        int t = lane + half * 32;
        int a = t >> 4, b = (t >> 2) & 3, c = t & 3;
        float wx = __shfl_sync(0xffffffffu, e, a);
        float wy = __shfl_sync(0xffffffffu, e, 4 + b);
        float wz = __shfl_sync(0xffffffffu, e, 8 + c);
        int cx = (bx + a - 1) & 127;
        int cy = (by + b - 1) & 127;
        int cz = (bz + c - 1) & 127;
        float w = wx * wy * wz;
        int idx = ((cz << 7) + cy << 7) + cx;
        if (half == 0) { w0 = w; idx0 = idx; } else { w1 = w; idx1 = idx; }
    }
}

// 8 warps (particles) per 256-thread block
__global__ __launch_bounds__(256)
void k_scatter(const float* __restrict__ pos, int n) {
    int i = (blockIdx.x * 256 + threadIdx.x) >> 5;
    int lane = threadIdx.x & 31;
    if (i >= n) return;
    float w0, w1; int idx0, idx1;
    warp_window(pos, i, lane, w0, idx0, w1, idx1);
    float s = __ldg(&g_s[i]);
    atomicAdd(&g_field0[idx0], w0 * s);
    atomicAdd(&g_field0[idx1], w1 * s);
}

__global__ __launch_bounds__(256)
void k_gather(const float* __restrict__ pos, float* __restrict__ out, int n) {
    int i = (blockIdx.x * 256 + threadIdx.x) >> 5;
    int lane = threadIdx.x & 31;
    if (i >= n) return;
    float w0, w1; int idx0, idx1;
    warp_window(pos, i, lane, w0, idx0, w1, idx1);
    float v = w0 * __ldg(&g_field0[idx0]) + w1 * __ldg(&g_field0[idx1]);
    #pragma unroll
    for (int o = 16; o; o >>= 1) v += __shfl_xor_sync(0xffffffffu, v, o);
    if (lane == 0) out[i] = v;
}

// ---------------------------------------------------------------------------
// z-axis circular conv: g_field0 -> g_field1. NO smem: each thread register-
// slides 8+2*RAD coalesced gmem (L2-hot) reads -> 8 outputs.
// Block = 256 threads (32 x-lanes x 8 z-groups). Grid = (4, 2, 128).
// ---------------------------------------------------------------------------
__global__ __launch_bounds__(256)
void k_convz(Taps tp) {
    int tx = threadIdx.x & 31;
    int tz = threadIdx.x >> 5;            // 0..7
    int x  = blockIdx.x * 32 + tx;
    int z0 = blockIdx.y * 64 + tz * 8;
    int yy = blockIdx.z;
    const float* base = g_field0 + (yy << 7) + x;
    float v[8 + 2 * RAD];
    #pragma unroll
    for (int j = 0; j < 8 + 2 * RAD; j++)
        v[j] = __ldg(&base[((z0 + j - RAD) & 127) << 14]);
    float* ob = g_field1 + (yy << 7) + x;
    #pragma unroll
    for (int k = 0; k < 8; k++) {
        float acc = tp.t[0] * v[k + RAD];
        #pragma unroll
        for (int d = 1; d <= RAD; d++)
            acc += tp.t[d] * (v[k + RAD + d] + v[k + RAD - d]);
        ob[(z0 + k) << 14] = acc;
    }
}

// ---------------------------------------------------------------------------
// Fused y-then-x conv on a 64-row half of one z-slice: g_field1 -> g_field0.
// y-conv reads DIRECTLY from gmem (coalesced, L2-hot) into register window,
// writes transposed smem b (odd stride 65 -> conflict-free); single barrier;
// x-conv register-slides over b and float4-stores to gmem.
// Grid = 256 blocks (2 halves x 128 slices) x 512 threads, 33 KB smem.
// ---------------------------------------------------------------------------
__global__ __launch_bounds__(512)
void k_slab(Taps tp) {
    __shared__ float b[NGRID][65];        // (x, y-local) transposed
    int tid = threadIdx.x;
    int zslice = blockIdx.x >> 1;
    int ybase  = (blockIdx.x & 1) * 64;
    const float* in   = g_field1 + (zslice << 14);
    float*       outp = g_field0 + (zslice << 14);

    float v[16 + 2 * RAD];
    // y-conv: gmem -> b. Thread: fixed x = tid&127, y-run of 16.
    {
        int x   = tid & 127;
        int yl0 = (tid >> 7) * 16;        // 0,16,32,48
        #pragma unroll
        for (int j = 0; j < 16 + 2 * RAD; j++)
            v[j] = __ldg(&in[(((ybase + yl0 + j - RAD) & 127) << 7) + x]);
        #pragma unroll
        for (int k = 0; k < 16; k++) {
            float acc = tp.t[0] * v[k + RAD];
            #pragma unroll
            for (int d = 1; d <= RAD; d++)
                acc += tp.t[d] * (v[k + RAD + d] + v[k + RAD - d]);
            b[x][yl0 + k] = acc;          // stride 65 (odd) -> conflict-free
        }
    }
    __syncthreads();

    // x-conv: b -> gmem. Thread: fixed y-local = tid&63, x-run of 16.
    {
        int y  = tid & 63;
        int x0 = (tid >> 6) * 16;         // 0..112
        #pragma unroll
        for (int j = 0; j < 16 + 2 * RAD; j++)
            v[j] = b[(x0 + j - RAD) & 127][y];
        float4* op = reinterpret_cast<float4*>(outp + ((ybase + y) << 7) + x0);
        #pragma unroll
        for (int q = 0; q < 4; q++) {
            float r[4];
            #pragma unroll
            for (int m = 0; m < 4; m++) {
                int k = q * 4 + m;
                float acc = tp.t[0] * v[k + RAD];
                #pragma unroll
                for (int d = 1; d <= RAD; d++)
                    acc += tp.t[d] * (v[k + RAD + d] + v[k + RAD - d]);
                r[m] = acc;
            }
            op[q] = make_float4(r[0], r[1], r[2], r[3]);
        }
    }
}

// ---------------------------------------------------------------------------
// Host-side exact taps: inverse DFT of exp(-0.5*sig^2*k^2) with sig = h = L/NG.
// ---------------------------------------------------------------------------
static Taps make_taps() {
    Taps tp;
    for (int d = 0; d <= RAD; d++) {
        double acc = 1.0;  // m = 0
        for (int m = 1; m < 64; m++) {
            double a = M_PI * (double)m / 64.0;
            acc += 2.0 * exp(-0.5 * a * a) * cos(M_PI * (double)(m * d) / 64.0);
        }
        acc += exp(-0.5 * M_PI * M_PI) * cos(M_PI * (double)d);  // m = 64 (Nyquist)
        tp.t[d] = (float)(acc / 128.0);
    }
    return tp;
}

extern "C" void kernel_launch(void* const* d_in, const int* in_sizes, int n_in,
                              void* d_out, int out_size) {
    const int*   z   = (const int*)  d_in[0];
    const float* pos = (const float*)d_in[1];
    // d_in[2] = batch (all zeros, NBATCH=1) — unused
    const float* emb = (const float*)d_in[3];
    const float* W0  = (const float*)d_in[4];
    const float* b0  = (const float*)d_in[5];
    const float* W1  = (const float*)d_in[6];
    const float* b1  = (const float*)d_in[7];
    float* out = (float*)d_out;
    int n = in_sizes[0];

    Taps tp = make_taps();   // host double math; baked into the captured graph

    int wpb = 8;  // warps (particles) per block in scatter/gather
    k_zero_mlp<<<2048, 256>>>(z, emb, W0, b0, W1, b1, n);
    k_scatter<<<(n + wpb - 1) / wpb, 256>>>(pos, n);
    k_convz<<<dim3(4, 2, 128), 256>>>(tp);   // z-axis: f0 -> f1 (direct gmem sliding)
    k_slab<<<256, 512>>>(tp);                // y+x axes: f1 -> f0 (half-slice tiles)
    k_gather<<<(n + wpb - 1) / wpb, 256>>>(pos, out, n);
}

// round 11
// speedup vs baseline: 1.0009x; 1.0009x over previous
#include <cuda_runtime.h>
#include <math.h>

#define NGRID 128
#define NG3 (NGRID*NGRID*NGRID)
#define CCH 32
#define RAD 4          // conv kernel radius; neglected mass ~3e-6 relative
#define MAXN 32768

__device__ float g_field0[NG3];   // 8 MB (scatter target / slab output / gather src)
__device__ float g_field1[NG3];   // 8 MB (z-conv out / slab input)
__device__ float g_s[MAXN];       // per-particle channel-summed feature

struct Taps { float t[RAD + 1]; };

// ---------------------------------------------------------------------------
// Fused zero + MLP. Grid = 2048 blocks x 256 threads.
// ---------------------------------------------------------------------------
__global__ __launch_bounds__(256)
void k_zero_mlp(const int* __restrict__ z, const float* __restrict__ emb,
                const float* __restrict__ W0, const float* __restrict__ b0,
                const float* __restrict__ W1, const float* __restrict__ b1,
                int n) {
    int gtid = blockIdx.x * 256 + threadIdx.x;
    reinterpret_cast<float4*>(g_field0)[gtid] = make_float4(0.f, 0.f, 0.f, 0.f);

    int mlp_blocks = (n + 255) / 256;
    if ((int)blockIdx.x >= mlp_blocks) return;

    __shared__ float sEmb[128 * CCH];
    __shared__ float sW0[CCH * CCH];
    __shared__ float sW1[CCH * CCH];
    __shared__ float sb0[CCH], sb1[CCH];
    for (int i = threadIdx.x; i < 128 * CCH; i += 256) sEmb[i] = emb[i];
    for (int i = threadIdx.x; i < CCH * CCH; i += 256) { sW0[i] = W0[i]; sW1[i] = W1[i]; }
    if (threadIdx.x < CCH) { sb0[threadIdx.x] = b0[threadIdx.x]; sb1[threadIdx.x] = b1[threadIdx.x]; }
    __syncthreads();

    int i = gtid;
    if (i >= n) return;
    int zi = z[i];
    float x[CCH], y[CCH];
    #pragma unroll
    for (int c = 0; c < CCH; c++) x[c] = sEmb[zi * CCH + c];
    #pragma unroll
    for (int r = 0; r < CCH; r++) {
        float a = sb0[r];
        #pragma unroll
        for (int c = 0; c < CCH; c++) a += sW0[r * CCH + c] * x[c];
        y[r] = a / (1.f + __expf(-a));               // silu
    }
    float s = 0.f;
    #pragma unroll
    for (int r = 0; r < CCH; r++) {
        float a = sb1[r];
        #pragma unroll
        for (int c = 0; c < CCH; c++) a += sW1[r * CCH + c] * y[c];
        s += a / (1.f + __expf(-a));                 // silu, then channel-sum
    }
    g_s[i] = s;
}

// ---------------------------------------------------------------------------
// Separable window, one WARP per particle.
// ---------------------------------------------------------------------------
__device__ __forceinline__ void warp_window(const float* __restrict__ pos, int i, int lane,
                                            float& w0, int& idx0, float& w1, int& idx1) {
    const float h = 10.0f / 128.0f;     // exact in fp32
    const float inv = 1.0f / h;
    float px = fmodf(__ldg(&pos[3 * i + 0]), 10.0f);
    float py = fmodf(__ldg(&pos[3 * i + 1]), 10.0f);
    float pz = fmodf(__ldg(&pos[3 * i + 2]), 10.0f);
    int bx = (int)floorf(px * inv);
    int by = (int)floorf(py * inv);
    int bz = (int)floorf(pz * inv);

    // lanes 0..11: one exp each (axis = lane>>2, offset = lane&3)
    int ax = lane >> 2, off = lane & 3;
    float pw = (ax == 0) ? px : (ax == 1) ? py : pz;
    int   bb = (ax == 0) ? bx : (ax == 1) ? by : bz;
    int cc = bb + off - 1;
    float d = (pw - (float)cc * h) * inv;
    float e = __expf(-0.5f * d * d);

    #pragma unroll
    for (int half = 0; half < 2; half++) {
        int t = lane + half * 32;
        int a = t >> 4, b = (t >> 2) & 3, c = t & 3;
        float wx = __shfl_sync(0xffffffffu, e, a);
        float wy = __shfl_sync(0xffffffffu, e, 4 + b);
        float wz = __shfl_sync(0xffffffffu, e, 8 + c);
        int cx = (bx + a - 1) & 127;
        int cy = (by + b - 1) & 127;
        int cz = (bz + c - 1) & 127;
        float w = wx * wy * wz;
        int idx = ((cz << 7) + cy << 7) + cx;
        if (half == 0) { w0 = w; idx0 = idx; } else { w1 = w; idx1 = idx; }
    }
}

// 8 warps (particles) per 256-thread block
__global__ __launch_bounds__(256)
void k_scatter(const float* __restrict__ pos, int n) {
    int i = (blockIdx.x * 256 + threadIdx.x) >> 5;
    int lane = threadIdx.x & 31;
    if (i >= n) return;
    float w0, w1; int idx0, idx1;
    warp_window(pos, i, lane, w0, idx0, w1, idx1);
    float s = __ldg(&g_s[i]);
    atomicAdd(&g_field0[idx0], w0 * s);
    atomicAdd(&g_field0[idx1], w1 * s);
}

__global__ __launch_bounds__(256)
void k_gather(const float* __restrict__ pos, float* __restrict__ out, int n) {
    int i = (blockIdx.x * 256 + threadIdx.x) >> 5;
    int lane = threadIdx.x & 31;
    if (i >= n) return;
    float w0, w1; int idx0, idx1;
    warp_window(pos, i, lane, w0, idx0, w1, idx1);
    float v = w0 * __ldg(&g_field0[idx0]) + w1 * __ldg(&g_field0[idx1]);
    #pragma unroll
    for (int o = 16; o; o >>= 1) v += __shfl_xor_sync(0xffffffffu, v, o);
    if (lane == 0) out[i] = v;
}

// ---------------------------------------------------------------------------
// z-axis circular conv: g_field0 -> g_field1. NO smem: each thread register-
// slides 8+2*RAD coalesced gmem (L2-hot) reads -> 8 outputs.
// Block = 256 threads (32 x-lanes x 8 z-groups). Grid = (4, 2, 128).
// ---------------------------------------------------------------------------
__global__ __launch_bounds__(256)
void k_convz(Taps tp) {
    int tx = threadIdx.x & 31;
    int tz = threadIdx.x >> 5;            // 0..7
    int x  = blockIdx.x * 32 + tx;
    int z0 = blockIdx.y * 64 + tz * 8;
    int yy = blockIdx.z;
    const float* base = g_field0 + (yy << 7) + x;
    float v[8 + 2 * RAD];
    #pragma unroll
    for (int j = 0; j < 8 + 2 * RAD; j++)
        v[j] = __ldg(&base[((z0 + j - RAD) & 127) << 14]);
    float* ob = g_field1 + (yy << 7) + x;
    #pragma unroll
    for (int k = 0; k < 8; k++) {
        float acc = tp.t[0] * v[k + RAD];
        #pragma unroll
        for (int d = 1; d <= RAD; d++)
            acc += tp.t[d] * (v[k + RAD + d] + v[k + RAD - d]);
        ob[(z0 + k) << 14] = acc;
    }
}

// ---------------------------------------------------------------------------
// Fused y-then-x conv on a 32-row y-strip of one z-slice: g_field1 -> g_field0.
// y-conv reads DIRECTLY from gmem (coalesced, L2-hot) into register window,
// writes transposed smem b (odd stride 33 -> conflict-free); single barrier;
// x-conv register-slides over b and float4-stores to gmem.
// 8 outputs/thread. Grid = 512 blocks (4 strips x 128 slices) x 512 threads,
// ~17 KB smem -> ~4 blocks/SM, 262K threads total.
// ---------------------------------------------------------------------------
__global__ __launch_bounds__(512)
void k_slab(Taps tp) {
    __shared__ float b[NGRID][33];        // (x, y-local) transposed
    int tid = threadIdx.x;
    int zslice = blockIdx.x >> 2;
    int ybase  = (blockIdx.x & 3) * 32;
    const float* in   = g_field1 + (zslice << 14);
    float*       outp = g_field0 + (zslice << 14);

    float v[8 + 2 * RAD];
    // y-conv: gmem -> b. Thread: fixed x = tid&127, y-run of 8.
    {
        int x   = tid & 127;
        int yl0 = (tid >> 7) * 8;         // 0,8,16,24
        #pragma unroll
        for (int j = 0; j < 8 + 2 * RAD; j++)
            v[j] = __ldg(&in[(((ybase + yl0 + j - RAD) & 127) << 7) + x]);
        #pragma unroll
        for (int k = 0; k < 8; k++) {
            float acc = tp.t[0] * v[k + RAD];
            #pragma unroll
            for (int d = 1; d <= RAD; d++)
                acc += tp.t[d] * (v[k + RAD + d] + v[k + RAD - d]);
            b[x][yl0 + k] = acc;          // stride 33 (odd) -> conflict-free
        }
    }
    __syncthreads();

    // x-conv: b -> gmem. Thread: fixed y-local = tid&31 (lane), x-run of 8.
    {
        int y  = tid & 31;
        int x0 = (tid >> 5) * 8;          // 0..120
        #pragma unroll
        for (int j = 0; j < 8 + 2 * RAD; j++)
            v[j] = b[(x0 + j - RAD) & 127][y];
        float4* op = reinterpret_cast<float4*>(outp + ((ybase + y) << 7) + x0);
        #pragma unroll
        for (int q = 0; q < 2; q++) {
            float r[4];
            #pragma unroll
            for (int m = 0; m < 4; m++) {
                int k = q * 4 + m;
                float acc = tp.t[0] * v[k + RAD];
                #pragma unroll
                for (int d = 1; d <= RAD; d++)
                    acc += tp.t[d] * (v[k + RAD + d] + v[k + RAD - d]);
                r[m] = acc;
            }
            op[q] = make_float4(r[0], r[1], r[2], r[3]);
        }
    }
}

// ---------------------------------------------------------------------------
// Host-side exact taps: inverse DFT of exp(-0.5*sig^2*k^2) with sig = h = L/NG.
// ---------------------------------------------------------------------------
static Taps make_taps() {
    Taps tp;
    for (int d = 0; d <= RAD; d++) {
        double acc = 1.0;  // m = 0
        for (int m = 1; m < 64; m++) {
            double a = M_PI * (double)m / 64.0;
            acc += 2.0 * exp(-0.5 * a * a) * cos(M_PI * (double)(m * d) / 64.0);
        }
        acc += exp(-0.5 * M_PI * M_PI) * cos(M_PI * (double)d);  // m = 64 (Nyquist)
        tp.t[d] = (float)(acc / 128.0);
    }
    return tp;
}

extern "C" void kernel_launch(void* const* d_in, const int* in_sizes, int n_in,
                              void* d_out, int out_size) {
    const int*   z   = (const int*)  d_in[0];
    const float* pos = (const float*)d_in[1];
    // d_in[2] = batch (all zeros, NBATCH=1) — unused
    const float* emb = (const float*)d_in[3];
    const float* W0  = (const float*)d_in[4];
    const float* b0  = (const float*)d_in[5];
    const float* W1  = (const float*)d_in[6];
    const float* b1  = (const float*)d_in[7];
    float* out = (float*)d_out;
    int n = in_sizes[0];

    Taps tp = make_taps();   // host double math; baked into the captured graph

    int wpb = 8;  // warps (particles) per block in scatter/gather
    k_zero_mlp<<<2048, 256>>>(z, emb, W0, b0, W1, b1, n);
    k_scatter<<<(n + wpb - 1) / wpb, 256>>>(pos, n);
    k_convz<<<dim3(4, 2, 128), 256>>>(tp);   // z-axis: f0 -> f1 (direct gmem sliding)
    k_slab<<<512, 512>>>(tp);                // y+x axes: f1 -> f0 (32-row strips)
    k_gather<<<(n + wpb - 1) / wpb, 256>>>(pos, out, n);
}